// round 1
// baseline (speedup 1.0000x reference)
#include <cuda_runtime.h>
#include <cuda_bf16.h>

// EdgeDecoder: per-edge bilinear scores over 5 relations + softmax-expected rating.
//   z_user  [100000, 64] f32
//   z_movie [ 50000, 64] f32
//   rel_emb [     5, 64] f32
//   edge_label_index [2, E] int (32 or 64 — detected at runtime)
//   out [E] f32
//
// Strategy: 16 threads/edge; each lane float4-loads 16B of each embedding row
// (16*16B = 256B fully coalesced per row), computes 5 partial dots against
// register-resident rel_emb, butterfly-reduces within the 16-lane group,
// group leader does the 5-way softmax + expected value.

constexpr int H = 64;
constexpr int R = 5;

__device__ int g_idx_is64;

__global__ void detect_idx_dtype_kernel(const void* __restrict__ edge_idx) {
    // Interpret the first 8 entries as int64. True int64 indices are all in
    // [0, 50000). int32 data reinterpreted as int64 gives lo + hi*2^32 with
    // hi ~ U[0,50000): passing all 8 checks has probability ~ (2e-5)^8.
    const long long* p = (const long long*)edge_idx;
    int is64 = 1;
    #pragma unroll
    for (int i = 0; i < 8; i++) {
        long long v = p[i];
        if (v < 0 || v >= 50000) { is64 = 0; }
    }
    g_idx_is64 = is64;
}

__global__ __launch_bounds__(256) void edge_decoder_kernel(
    const float* __restrict__ z_user,
    const float* __restrict__ z_movie,
    const float* __restrict__ rel_emb,
    const void* __restrict__ edge_idx,
    float* __restrict__ out,
    int E)
{
    const int tid = blockIdx.x * blockDim.x + threadIdx.x;
    const int sub = threadIdx.x & 15;   // lane within the 16-thread edge group
    const int e   = tid >> 4;           // edge id

    // Preload rel_emb slice for this lane: rel[r][4*sub .. 4*sub+3].
    // 1.25KB total table — permanently L1/L2 resident, broadcast across groups.
    float4 rel[R];
    #pragma unroll
    for (int r = 0; r < R; r++)
        rel[r] = *reinterpret_cast<const float4*>(rel_emb + r * H + 4 * sub);

    if (e >= E) return;

    long long s, d;
    if (g_idx_is64) {
        const long long* p = (const long long*)edge_idx;
        s = __ldg(p + e);
        d = __ldg(p + (long long)E + e);
    } else {
        const int* p = (const int*)edge_idx;
        s = __ldg(p + e);
        d = __ldg(p + E + e);
    }

    const float4 zs = *reinterpret_cast<const float4*>(z_user  + s * H + 4 * sub);
    const float4 zd = *reinterpret_cast<const float4*>(z_movie + d * H + 4 * sub);

    const float px = zs.x * zd.x;
    const float py = zs.y * zd.y;
    const float pz = zs.z * zd.z;
    const float pw = zs.w * zd.w;

    float sc[R];
    #pragma unroll
    for (int r = 0; r < R; r++)
        sc[r] = fmaf(px, rel[r].x, fmaf(py, rel[r].y, fmaf(pz, rel[r].z, pw * rel[r].w)));

    // Butterfly reduce across the 16-lane group (xor offsets stay in-group).
    #pragma unroll
    for (int off = 8; off >= 1; off >>= 1) {
        #pragma unroll
        for (int r = 0; r < R; r++)
            sc[r] += __shfl_xor_sync(0xffffffffu, sc[r], off);
    }

    if (sub == 0) {
        float m = sc[0];
        #pragma unroll
        for (int r = 1; r < R; r++) m = fmaxf(m, sc[r]);
        float den = 0.f, num = 0.f;
        #pragma unroll
        for (int r = 0; r < R; r++) {
            float ex = __expf(sc[r] - m);
            den += ex;
            num += ex * (float)r;
        }
        out[e] = num / den;
    }
}

extern "C" void kernel_launch(void* const* d_in, const int* in_sizes, int n_in,
                              void* d_out, int out_size) {
    const float* z_user  = (const float*)d_in[0];
    const float* z_movie = (const float*)d_in[1];
    const float* rel_emb = (const float*)d_in[2];
    const void*  eidx    = d_in[3];
    float* out = (float*)d_out;

    const int E = out_size;  // one rating per edge

    detect_idx_dtype_kernel<<<1, 1>>>(eidx);

    const int threads = 256;
    const long long total_threads = (long long)E * 16;
    const int blocks = (int)((total_threads + threads - 1) / threads);
    edge_decoder_kernel<<<blocks, threads>>>(z_user, z_movie, rel_emb, eidx, out, E);
}